// round 1
// baseline (speedup 1.0000x reference)
#include <cuda_runtime.h>
#include <math.h>

#define N_NODES 50000
#define N_EDGES 800000
#define DIM     256
#define DEPTH   4
#define N_REL   4
#define LN_EPS  1e-5f

// ---------------------------------------------------------------------------
// Scratch (device globals: allocation-free per harness rules)
// ---------------------------------------------------------------------------
__device__ float g_H[(size_t)N_NODES * (N_REL * DIM)];   // per-relation transforms  [N, 1024]
__device__ float g_OUT[(size_t)N_NODES * DIM];           // agg + X@root + bias      [N, 256]
__device__ float g_bufA[(size_t)N_NODES * DIM];          // X ping
__device__ float g_bufB[(size_t)N_NODES * DIM];          // X pong
__device__ int   g_cnt[N_NODES * N_REL];                 // per (dst, rel) in-degree

// ---------------------------------------------------------------------------
// Utility kernels
// ---------------------------------------------------------------------------
__global__ void zero_cnt_kernel() {
    int i = blockIdx.x * blockDim.x + threadIdx.x;
    if (i < N_NODES * N_REL) g_cnt[i] = 0;
}

__global__ void count_kernel(const int* __restrict__ dst, const int* __restrict__ et) {
    int e = blockIdx.x * blockDim.x + threadIdx.x;
    if (e < N_EDGES) atomicAdd(&g_cnt[dst[e] * N_REL + et[e]], 1);
}

__global__ void copy_f4_kernel(const float4* __restrict__ src, float4* __restrict__ dst, int n) {
    int i = blockIdx.x * blockDim.x + threadIdx.x;
    if (i < n) dst[i] = src[i];
}

// ---------------------------------------------------------------------------
// GEMM: C = X[50000,256] @ Wcat[256,1280]
//   col tiles 0..7  -> relation weights r = bc/2 -> write g_H [N,1024]
//   col tiles 8..9  -> root matrix + bias        -> write g_OUT [N,256]
// 128x128x16 tile, 256 threads, 8x8 (split 4+4) micro-tile.
// ---------------------------------------------------------------------------
__global__ __launch_bounds__(256, 2) void gemm_kernel(
    const float* __restrict__ X,
    const float* __restrict__ W4,     // weights[l] : [4,256,256]
    const float* __restrict__ root,   // roots[l]   : [256,256]
    const float* __restrict__ bias,   // biases[l]  : [256]
    float* __restrict__ H,
    float* __restrict__ OUT)
{
    const int bc   = blockIdx.x;        // 0..9
    const int row0 = blockIdx.y * 128;
    const int tid  = threadIdx.x;

    const bool isroot = (bc >= 8);
    const float* B;
    float* Cbase;
    int ldc, colbase;
    if (!isroot) {
        int r   = bc >> 1;
        colbase = (bc & 1) * 128;
        B       = W4 + (size_t)r * DIM * DIM + colbase;
        Cbase   = H + (size_t)r * DIM + colbase;
        ldc     = N_REL * DIM;          // 1024
    } else {
        colbase = (bc - 8) * 128;
        B       = root + colbase;
        Cbase   = OUT + colbase;
        ldc     = DIM;
    }

    __shared__ float As[16][128];
    __shared__ float Bs[16][128];

    const int tx = tid & 15;
    const int ty = tid >> 4;

    float acc[8][8];
    #pragma unroll
    for (int i = 0; i < 8; i++)
        #pragma unroll
        for (int j = 0; j < 8; j++) acc[i][j] = 0.f;

    const int arow = tid >> 2;   // 0..63
    const int acol = tid & 3;    // 0..3
    const int brow = tid >> 5;   // 0..7
    const int bcol = tid & 31;   // 0..31

    for (int k0 = 0; k0 < DIM; k0 += 16) {
        #pragma unroll
        for (int i = 0; i < 2; i++) {
            int m  = arow + 64 * i;
            int gr = row0 + m;
            float4 v = make_float4(0.f, 0.f, 0.f, 0.f);
            if (gr < N_NODES)
                v = *(const float4*)(X + (size_t)gr * DIM + k0 + acol * 4);
            As[acol * 4 + 0][m] = v.x;
            As[acol * 4 + 1][m] = v.y;
            As[acol * 4 + 2][m] = v.z;
            As[acol * 4 + 3][m] = v.w;
        }
        #pragma unroll
        for (int i = 0; i < 2; i++) {
            int k = brow + 8 * i;
            *(float4*)&Bs[k][bcol * 4] =
                *(const float4*)(B + (size_t)(k0 + k) * DIM + bcol * 4);
        }
        __syncthreads();

        #pragma unroll
        for (int k = 0; k < 16; k++) {
            float a[8], b[8];
            *(float4*)&a[0] = *(const float4*)&As[k][ty * 4];
            *(float4*)&a[4] = *(const float4*)&As[k][64 + ty * 4];
            *(float4*)&b[0] = *(const float4*)&Bs[k][tx * 4];
            *(float4*)&b[4] = *(const float4*)&Bs[k][64 + tx * 4];
            #pragma unroll
            for (int i = 0; i < 8; i++)
                #pragma unroll
                for (int j = 0; j < 8; j++)
                    acc[i][j] = fmaf(a[i], b[j], acc[i][j]);
        }
        __syncthreads();
    }

    float bv[8] = {0.f, 0.f, 0.f, 0.f, 0.f, 0.f, 0.f, 0.f};
    if (isroot) {
        #pragma unroll
        for (int j = 0; j < 4; j++) {
            bv[j]     = bias[colbase + tx * 4 + j];
            bv[4 + j] = bias[colbase + 64 + tx * 4 + j];
        }
    }

    #pragma unroll
    for (int i = 0; i < 8; i++) {
        int m  = (i < 4) ? (ty * 4 + i) : (64 + ty * 4 + (i - 4));
        int gr = row0 + m;
        if (gr < N_NODES) {
            float* Crow = Cbase + (size_t)gr * ldc;
            float4 v0 = make_float4(acc[i][0] + bv[0], acc[i][1] + bv[1],
                                    acc[i][2] + bv[2], acc[i][3] + bv[3]);
            float4 v1 = make_float4(acc[i][4] + bv[4], acc[i][5] + bv[5],
                                    acc[i][6] + bv[6], acc[i][7] + bv[7]);
            *(float4*)(Crow + tx * 4)      = v0;
            *(float4*)(Crow + 64 + tx * 4) = v1;
        }
    }
}

// ---------------------------------------------------------------------------
// Edge aggregation: OUT[dst] += inv_deg * H[src, etype*256 : +256]
// 64 threads per edge, float4 lanes, vectorized fp32 reduction (sm_90+).
// ---------------------------------------------------------------------------
__global__ void edge_kernel(const float* __restrict__ H,
                            const int* __restrict__ src,
                            const int* __restrict__ dst,
                            const int* __restrict__ et,
                            const int* __restrict__ cnt,
                            float* __restrict__ OUT)
{
    int e    = blockIdx.x * 4 + (threadIdx.x >> 6);
    int lane = threadIdx.x & 63;

    int s = src[e];
    int d = dst[e];
    int t = et[e];
    int c = cnt[d * N_REL + t];
    float inv = 1.0f / (float)(c > 1 ? c : 1);

    float4 v = *(const float4*)(H + (size_t)s * (N_REL * DIM) + t * DIM + lane * 4);
    v.x *= inv; v.y *= inv; v.z *= inv; v.w *= inv;

    float* p = OUT + (size_t)d * DIM + lane * 4;
    asm volatile("red.global.add.v4.f32 [%0], {%1, %2, %3, %4};"
                 :: "l"(p), "f"(v.x), "f"(v.y), "f"(v.z), "f"(v.w)
                 : "memory");
}

// ---------------------------------------------------------------------------
// LayerNorm + ELU + residual (one block of 256 threads per node row)
// ---------------------------------------------------------------------------
__device__ __forceinline__ float block_sum_256(float v, float* sh) {
    #pragma unroll
    for (int o = 16; o > 0; o >>= 1) v += __shfl_xor_sync(0xffffffffu, v, o);
    __syncthreads();   // protect sh across repeated calls
    if ((threadIdx.x & 31) == 0) sh[threadIdx.x >> 5] = v;
    __syncthreads();
    float s = 0.f;
    #pragma unroll
    for (int i = 0; i < 8; i++) s += sh[i];
    return s;
}

__global__ void ln_kernel(const float* __restrict__ OUT,
                          const float* __restrict__ Xin,
                          const float* __restrict__ gamma,
                          const float* __restrict__ beta,
                          float* __restrict__ Xout)
{
    __shared__ float sh[8];
    int n = blockIdx.x;
    int j = threadIdx.x;

    float v  = OUT[(size_t)n * DIM + j];
    float mu = block_sum_256(v, sh) * (1.0f / DIM);
    float dl = v - mu;
    float var = block_sum_256(dl * dl, sh) * (1.0f / DIM);

    float y = dl * rsqrtf(var + LN_EPS) * gamma[j] + beta[j];
    y = (y > 0.f) ? y : expm1f(y);
    Xout[(size_t)n * DIM + j] = y + Xin[(size_t)n * DIM + j];
}

// ---------------------------------------------------------------------------
// Driver
// ---------------------------------------------------------------------------
extern "C" void kernel_launch(void* const* d_in, const int* in_sizes, int n_in,
                              void* d_out, int out_size)
{
    const float* node    = (const float*)d_in[0];
    const float* weights = (const float*)d_in[1];   // [4,4,256,256]
    const float* roots   = (const float*)d_in[2];   // [4,256,256]
    const float* biases  = (const float*)d_in[3];   // [4,256]
    const float* gamma   = (const float*)d_in[4];   // [4,256]
    const float* beta    = (const float*)d_in[5];   // [4,256]
    const int*   eidx    = (const int*)d_in[6];     // [2,800000]
    const int*   etype   = (const int*)d_in[7];     // [800000]
    const int*   srcv    = eidx;
    const int*   dstv    = eidx + N_EDGES;
    float*       out     = (float*)d_out;

    float *H, *OUTb, *bufA, *bufB;
    int* cnt;
    cudaGetSymbolAddress((void**)&H,    g_H);
    cudaGetSymbolAddress((void**)&OUTb, g_OUT);
    cudaGetSymbolAddress((void**)&bufA, g_bufA);
    cudaGetSymbolAddress((void**)&bufB, g_bufB);
    cudaGetSymbolAddress((void**)&cnt,  g_cnt);

    // in-degree histogram (edge-structure only, once per launch)
    zero_cnt_kernel<<<(N_NODES * N_REL + 255) / 256, 256>>>();
    count_kernel<<<(N_EDGES + 255) / 256, 256>>>(dstv, etype);

    // X0 = node_embedding
    const int nf4 = N_NODES * DIM / 4;
    copy_f4_kernel<<<(nf4 + 255) / 256, 256>>>((const float4*)node, (float4*)bufA, nf4);

    for (int l = 0; l < DEPTH; l++) {
        const float* Xin  = (l & 1) ? bufB : bufA;
        float*       Xout = (l & 1) ? bufA : bufB;

        gemm_kernel<<<dim3(10, 391), 256>>>(
            Xin,
            weights + (size_t)l * N_REL * DIM * DIM,
            roots   + (size_t)l * DIM * DIM,
            biases  + (size_t)l * DIM,
            H, OUTb);

        edge_kernel<<<N_EDGES / 4, 256>>>(H, srcv, dstv, etype, cnt, OUTb);

        ln_kernel<<<N_NODES, 256>>>(OUTb, Xin, gamma + l * DIM, beta + l * DIM, Xout);
    }

    // after 4 layers result is in bufA
    copy_f4_kernel<<<(nf4 + 255) / 256, 256>>>((const float4*)bufA, (float4*)out, nf4);
}

// round 2
// speedup vs baseline: 1.0009x; 1.0009x over previous
#include <cuda_runtime.h>
#include <math.h>

#define N_NODES 50000
#define N_EDGES 800000
#define DIM     256
#define DEPTH   4
#define N_REL   4
#define LN_EPS  1e-5f

// ---------------------------------------------------------------------------
// Scratch (device globals: allocation-free per harness rules)
// ---------------------------------------------------------------------------
__device__ float g_H[(size_t)N_NODES * (N_REL * DIM)];   // per-relation transforms  [N, 1024]
__device__ float g_OUT[(size_t)N_NODES * DIM];           // agg + X@root + bias      [N, 256]
__device__ float g_bufA[(size_t)N_NODES * DIM];          // X ping
__device__ float g_bufB[(size_t)N_NODES * DIM];          // X pong
__device__ int   g_cnt[N_NODES * N_REL];                 // per (dst, rel) in-degree

// ---------------------------------------------------------------------------
// Utility kernels
// ---------------------------------------------------------------------------
__global__ void zero_cnt_kernel() {
    int i = blockIdx.x * blockDim.x + threadIdx.x;
    if (i < N_NODES * N_REL) g_cnt[i] = 0;
}

__global__ void count_kernel(const int* __restrict__ dst, const int* __restrict__ et) {
    int e = blockIdx.x * blockDim.x + threadIdx.x;
    if (e < N_EDGES) atomicAdd(&g_cnt[dst[e] * N_REL + et[e]], 1);
}

__global__ void copy_f4_kernel(const float4* __restrict__ src, float4* __restrict__ dst, int n) {
    int i = blockIdx.x * blockDim.x + threadIdx.x;
    if (i < n) dst[i] = src[i];
}

// ---------------------------------------------------------------------------
// GEMM: C = X[50000,256] @ Wcat[256,1280]
//   col tiles 0..7  -> relation weights r = bc/2 -> write g_H [N,1024]
//   col tiles 8..9  -> root matrix + bias        -> write g_OUT [N,256]
// 128x128x16 tile, 256 threads, 8x8 (split 4+4) micro-tile.
// ---------------------------------------------------------------------------
__global__ __launch_bounds__(256, 2) void gemm_kernel(
    const float* __restrict__ X,
    const float* __restrict__ W4,     // weights[l] : [4,256,256]
    const float* __restrict__ root,   // roots[l]   : [256,256]
    const float* __restrict__ bias,   // biases[l]  : [256]
    float* __restrict__ H,
    float* __restrict__ OUT)
{
    const int bc   = blockIdx.x;        // 0..9
    const int row0 = blockIdx.y * 128;
    const int tid  = threadIdx.x;

    const bool isroot = (bc >= 8);
    const float* B;
    float* Cbase;
    int ldc, colbase;
    if (!isroot) {
        int r   = bc >> 1;
        colbase = (bc & 1) * 128;
        B       = W4 + (size_t)r * DIM * DIM + colbase;
        Cbase   = H + (size_t)r * DIM + colbase;
        ldc     = N_REL * DIM;          // 1024
    } else {
        colbase = (bc - 8) * 128;
        B       = root + colbase;
        Cbase   = OUT + colbase;
        ldc     = DIM;
    }

    __shared__ float As[16][128];
    __shared__ float Bs[16][128];

    const int tx = tid & 15;
    const int ty = tid >> 4;

    float acc[8][8];
    #pragma unroll
    for (int i = 0; i < 8; i++)
        #pragma unroll
        for (int j = 0; j < 8; j++) acc[i][j] = 0.f;

    const int arow = tid >> 2;   // 0..63
    const int acol = tid & 3;    // 0..3
    const int brow = tid >> 5;   // 0..7
    const int bcol = tid & 31;   // 0..31

    for (int k0 = 0; k0 < DIM; k0 += 16) {
        #pragma unroll
        for (int i = 0; i < 2; i++) {
            int m  = arow + 64 * i;
            int gr = row0 + m;
            float4 v = make_float4(0.f, 0.f, 0.f, 0.f);
            if (gr < N_NODES)
                v = *(const float4*)(X + (size_t)gr * DIM + k0 + acol * 4);
            As[acol * 4 + 0][m] = v.x;
            As[acol * 4 + 1][m] = v.y;
            As[acol * 4 + 2][m] = v.z;
            As[acol * 4 + 3][m] = v.w;
        }
        #pragma unroll
        for (int i = 0; i < 2; i++) {
            int k = brow + 8 * i;
            *(float4*)&Bs[k][bcol * 4] =
                *(const float4*)(B + (size_t)(k0 + k) * DIM + bcol * 4);
        }
        __syncthreads();

        #pragma unroll
        for (int k = 0; k < 16; k++) {
            float a[8], b[8];
            *(float4*)&a[0] = *(const float4*)&As[k][ty * 4];
            *(float4*)&a[4] = *(const float4*)&As[k][64 + ty * 4];
            *(float4*)&b[0] = *(const float4*)&Bs[k][tx * 4];
            *(float4*)&b[4] = *(const float4*)&Bs[k][64 + tx * 4];
            #pragma unroll
            for (int i = 0; i < 8; i++)
                #pragma unroll
                for (int j = 0; j < 8; j++)
                    acc[i][j] = fmaf(a[i], b[j], acc[i][j]);
        }
        __syncthreads();
    }

    float bv[8] = {0.f, 0.f, 0.f, 0.f, 0.f, 0.f, 0.f, 0.f};
    if (isroot) {
        #pragma unroll
        for (int j = 0; j < 4; j++) {
            bv[j]     = bias[colbase + tx * 4 + j];
            bv[4 + j] = bias[colbase + 64 + tx * 4 + j];
        }
    }

    #pragma unroll
    for (int i = 0; i < 8; i++) {
        int m  = (i < 4) ? (ty * 4 + i) : (64 + ty * 4 + (i - 4));
        int gr = row0 + m;
        if (gr < N_NODES) {
            float* Crow = Cbase + (size_t)gr * ldc;
            float4 v0 = make_float4(acc[i][0] + bv[0], acc[i][1] + bv[1],
                                    acc[i][2] + bv[2], acc[i][3] + bv[3]);
            float4 v1 = make_float4(acc[i][4] + bv[4], acc[i][5] + bv[5],
                                    acc[i][6] + bv[6], acc[i][7] + bv[7]);
            *(float4*)(Crow + tx * 4)      = v0;
            *(float4*)(Crow + 64 + tx * 4) = v1;
        }
    }
}

// ---------------------------------------------------------------------------
// Edge aggregation: OUT[dst] += inv_deg * H[src, etype*256 : +256]
// 64 threads per edge, float4 lanes, vectorized fp32 reduction (sm_90+).
// ---------------------------------------------------------------------------
__global__ void edge_kernel(const float* __restrict__ H,
                            const int* __restrict__ src,
                            const int* __restrict__ dst,
                            const int* __restrict__ et,
                            const int* __restrict__ cnt,
                            float* __restrict__ OUT)
{
    int e    = blockIdx.x * 4 + (threadIdx.x >> 6);
    int lane = threadIdx.x & 63;

    int s = src[e];
    int d = dst[e];
    int t = et[e];
    int c = cnt[d * N_REL + t];
    float inv = 1.0f / (float)(c > 1 ? c : 1);

    float4 v = *(const float4*)(H + (size_t)s * (N_REL * DIM) + t * DIM + lane * 4);
    v.x *= inv; v.y *= inv; v.z *= inv; v.w *= inv;

    float* p = OUT + (size_t)d * DIM + lane * 4;
    asm volatile("red.global.add.v4.f32 [%0], {%1, %2, %3, %4};"
                 :: "l"(p), "f"(v.x), "f"(v.y), "f"(v.z), "f"(v.w)
                 : "memory");
}

// ---------------------------------------------------------------------------
// LayerNorm + ELU + residual (one block of 256 threads per node row)
// ---------------------------------------------------------------------------
__device__ __forceinline__ float block_sum_256(float v, float* sh) {
    #pragma unroll
    for (int o = 16; o > 0; o >>= 1) v += __shfl_xor_sync(0xffffffffu, v, o);
    __syncthreads();   // protect sh across repeated calls
    if ((threadIdx.x & 31) == 0) sh[threadIdx.x >> 5] = v;
    __syncthreads();
    float s = 0.f;
    #pragma unroll
    for (int i = 0; i < 8; i++) s += sh[i];
    return s;
}

__global__ void ln_kernel(const float* __restrict__ OUT,
                          const float* __restrict__ Xin,
                          const float* __restrict__ gamma,
                          const float* __restrict__ beta,
                          float* __restrict__ Xout)
{
    __shared__ float sh[8];
    int n = blockIdx.x;
    int j = threadIdx.x;

    float v  = OUT[(size_t)n * DIM + j];
    float mu = block_sum_256(v, sh) * (1.0f / DIM);
    float dl = v - mu;
    float var = block_sum_256(dl * dl, sh) * (1.0f / DIM);

    float y = dl * rsqrtf(var + LN_EPS) * gamma[j] + beta[j];
    y = (y > 0.f) ? y : expm1f(y);
    Xout[(size_t)n * DIM + j] = y + Xin[(size_t)n * DIM + j];
}

// ---------------------------------------------------------------------------
// Driver
// ---------------------------------------------------------------------------
extern "C" void kernel_launch(void* const* d_in, const int* in_sizes, int n_in,
                              void* d_out, int out_size)
{
    const float* node    = (const float*)d_in[0];
    const float* weights = (const float*)d_in[1];   // [4,4,256,256]
    const float* roots   = (const float*)d_in[2];   // [4,256,256]
    const float* biases  = (const float*)d_in[3];   // [4,256]
    const float* gamma   = (const float*)d_in[4];   // [4,256]
    const float* beta    = (const float*)d_in[5];   // [4,256]
    const int*   eidx    = (const int*)d_in[6];     // [2,800000]
    const int*   etype   = (const int*)d_in[7];     // [800000]
    const int*   srcv    = eidx;
    const int*   dstv    = eidx + N_EDGES;
    float*       out     = (float*)d_out;

    float *H, *OUTb, *bufA, *bufB;
    int* cnt;
    cudaGetSymbolAddress((void**)&H,    g_H);
    cudaGetSymbolAddress((void**)&OUTb, g_OUT);
    cudaGetSymbolAddress((void**)&bufA, g_bufA);
    cudaGetSymbolAddress((void**)&bufB, g_bufB);
    cudaGetSymbolAddress((void**)&cnt,  g_cnt);

    // in-degree histogram (edge-structure only, once per launch)
    zero_cnt_kernel<<<(N_NODES * N_REL + 255) / 256, 256>>>();
    count_kernel<<<(N_EDGES + 255) / 256, 256>>>(dstv, etype);

    // X0 = node_embedding
    const int nf4 = N_NODES * DIM / 4;
    copy_f4_kernel<<<(nf4 + 255) / 256, 256>>>((const float4*)node, (float4*)bufA, nf4);

    for (int l = 0; l < DEPTH; l++) {
        const float* Xin  = (l & 1) ? bufB : bufA;
        float*       Xout = (l & 1) ? bufA : bufB;

        gemm_kernel<<<dim3(10, 391), 256>>>(
            Xin,
            weights + (size_t)l * N_REL * DIM * DIM,
            roots   + (size_t)l * DIM * DIM,
            biases  + (size_t)l * DIM,
            H, OUTb);

        edge_kernel<<<N_EDGES / 4, 256>>>(H, srcv, dstv, etype, cnt, OUTb);

        ln_kernel<<<N_NODES, 256>>>(OUTb, Xin, gamma + l * DIM, beta + l * DIM, Xout);
    }

    // after 4 layers result is in bufA
    copy_f4_kernel<<<(nf4 + 255) / 256, 256>>>((const float4*)bufA, (float4*)out, nf4);
}

// round 4
// speedup vs baseline: 1.4746x; 1.4733x over previous
#include <cuda_runtime.h>
#include <cuda_bf16.h>
#include <math.h>
#include <stdint.h>

#define N_NODES 50000
#define N_EDGES 800000
#define DIM     256
#define DEPTH   4
#define N_REL   4
#define LN_EPS  1e-5f
#define NCOL    1280          // 4 relations * 256 + root 256

typedef __nv_bfloat16 bf16;

// ---------------------------------------------------------------------------
// Scratch (device globals: allocation-free per harness rules)
// ---------------------------------------------------------------------------
__device__ float g_H[(size_t)N_NODES * (N_REL * DIM)];   // per-relation transforms [N,1024]
__device__ float g_OUT[(size_t)N_NODES * DIM];           // agg + X@root + bias
__device__ float g_bufA[(size_t)N_NODES * DIM];          // X ping
__device__ float g_bufB[(size_t)N_NODES * DIM];          // X pong
__device__ bf16  g_Xhi[(size_t)N_NODES * DIM];           // bf16 hi split of X
__device__ bf16  g_Xlo[(size_t)N_NODES * DIM];           // bf16 lo split of X
__device__ bf16  g_Bhi[(size_t)DEPTH * NCOL * DIM];      // W^T hi  [l][n][k]
__device__ bf16  g_Blo[(size_t)DEPTH * NCOL * DIM];      // W^T lo
__device__ int   g_cnt[N_NODES * N_REL];

// ---------------------------------------------------------------------------
// PTX helpers (plain sm_80-era instructions -> assemble at target sm_103)
// ---------------------------------------------------------------------------
__device__ __forceinline__ uint32_t smem_u32(const void* p) {
    uint32_t a;
    asm("{ .reg .u64 t; cvta.to.shared.u64 t, %1; cvt.u32.u64 %0, t; }"
        : "=r"(a) : "l"(p));
    return a;
}

__device__ __forceinline__ void ldsm_x4(uint32_t& r0, uint32_t& r1,
                                        uint32_t& r2, uint32_t& r3, uint32_t addr) {
    asm volatile("ldmatrix.sync.aligned.m8n8.x4.shared.b16 {%0,%1,%2,%3}, [%4];"
                 : "=r"(r0), "=r"(r1), "=r"(r2), "=r"(r3) : "r"(addr));
}

#define MMA_BF16(c, a, b0v, b1v)                                             \
    asm volatile(                                                            \
        "mma.sync.aligned.m16n8k16.row.col.f32.bf16.bf16.f32 "               \
        "{%0,%1,%2,%3}, {%4,%5,%6,%7}, {%8,%9}, {%0,%1,%2,%3};"              \
        : "+f"((c)[0]), "+f"((c)[1]), "+f"((c)[2]), "+f"((c)[3])             \
        : "r"((a)[0]), "r"((a)[1]), "r"((a)[2]), "r"((a)[3]),                \
          "r"(b0v), "r"(b1v))

#define CPA16(dst, src)                                                      \
    asm volatile("cp.async.cg.shared.global [%0], [%1], 16;"                 \
                 :: "r"(dst), "l"(src) : "memory")
#define CPA_COMMIT() asm volatile("cp.async.commit_group;" ::: "memory")
#define CPA_WAIT(n)  asm volatile("cp.async.wait_group %0;" :: "n"(n) : "memory")

#define SW(o) ((uint32_t)(o) ^ ((((uint32_t)(o)) >> 3) & 0x70))

// ---------------------------------------------------------------------------
// Utility kernels
// ---------------------------------------------------------------------------
__global__ void zero_cnt_kernel() {
    int i = blockIdx.x * blockDim.x + threadIdx.x;
    if (i < N_NODES * N_REL) g_cnt[i] = 0;
}

__global__ void count_kernel(const int* __restrict__ dst, const int* __restrict__ et) {
    int e = blockIdx.x * blockDim.x + threadIdx.x;
    if (e < N_EDGES) atomicAdd(&g_cnt[dst[e] * N_REL + et[e]], 1);
}

__device__ __forceinline__ void bf16_split(float x, bf16& h, bf16& l) {
    h = __float2bfloat16(x);
    l = __float2bfloat16(x - __bfloat162float(h));
}

// split node embedding into bf16 hi/lo
__global__ void xsplit_kernel(const float* __restrict__ X,
                              bf16* __restrict__ hi, bf16* __restrict__ lo) {
    int i = blockIdx.x * 256 + threadIdx.x;
    bf16 h, l;
    bf16_split(X[i], h, l);
    hi[i] = h; lo[i] = l;
}

// transpose + split weights: Bhi/Blo[l][n][k] = split(W[l][rel][k][n] or root[l][k][n])
__global__ void wsplit_kernel(const float* __restrict__ W, const float* __restrict__ R,
                              bf16* __restrict__ Bhi, bf16* __restrict__ Blo) {
    __shared__ float t[32][33];
    int l  = blockIdx.z;
    int n0 = blockIdx.x * 32;
    int k0 = blockIdx.y * 32;
    int tx = threadIdx.x, ty = threadIdx.y;   // 32 x 8
    int rel = n0 >> 8;

    #pragma unroll
    for (int j = 0; j < 4; j++) {
        int k = k0 + ty + j * 8;
        float v;
        if (rel < 4)
            v = W[(((size_t)l * 4 + rel) * 256 + k) * 256 + (n0 & 255) + tx];
        else
            v = R[((size_t)l * 256 + k) * 256 + (n0 - 1024) + tx];
        t[ty + j * 8][tx] = v;
    }
    __syncthreads();
    #pragma unroll
    for (int j = 0; j < 4; j++) {
        int n = ty + j * 8;
        float x = t[tx][n];                    // = src[k0+tx][n0+n]
        bf16 h, lo;
        bf16_split(x, h, lo);
        size_t o = ((size_t)l * NCOL + n0 + n) * 256 + k0 + tx;
        Bhi[o] = h;
        Blo[o] = lo;
    }
}

// ---------------------------------------------------------------------------
// bf16 3-product GEMM via mma.sync: C[50000,1280] = X @ Wcat^T
//   C = Xhi*Bhi + Xlo*Bhi + Xhi*Blo  (fp32 accumulate)
// CTA tile 128x128, 8 warps (64x32 each), K chunks of 32 (hi|lo packed in
// one 128B SW128 row), 2-stage cp.async pipeline.
//   col tiles 0..7 -> g_H [N,1024];  col tiles 8..9 -> g_OUT (+bias)
// ---------------------------------------------------------------------------
#define STAGE_BYTES 32768          // A tile 16KB + B tile 16KB
#define SMEM_BYTES  (2 * STAGE_BYTES)

__device__ __forceinline__ void issue_stage(
    uint32_t smBase, int buf, int kc, int row0, int n0, int tid,
    const bf16* __restrict__ Xhi, const bf16* __restrict__ Xlo,
    const bf16* __restrict__ Bhi, const bf16* __restrict__ Blo)
{
    uint32_t aB = smBase + buf * STAGE_BYTES;
    uint32_t bB = aB + 16384;
    #pragma unroll
    for (int t = 0; t < 4; t++) {
        int j   = tid + t * 256;
        int row = j >> 3, ch = j & 7;
        int gr  = row0 + row;
        if (gr > N_NODES - 1) gr = N_NODES - 1;      // clamp; stores are guarded
        const bf16* src = (ch < 4 ? Xhi : Xlo) + (size_t)gr * 256 + kc * 32 + (ch & 3) * 8;
        CPA16(aB + SW(row * 128 + ch * 16), src);
    }
    #pragma unroll
    for (int t = 0; t < 4; t++) {
        int j   = tid + t * 256;
        int row = j >> 3, ch = j & 7;
        const bf16* src = (ch < 4 ? Bhi : Blo) + (size_t)(n0 + row) * 256 + kc * 32 + (ch & 3) * 8;
        CPA16(bB + SW(row * 128 + ch * 16), src);
    }
}

__global__ __launch_bounds__(256) void gemm_tc(
    const bf16* __restrict__ Xhi, const bf16* __restrict__ Xlo,
    const bf16* __restrict__ Bhi, const bf16* __restrict__ Blo,
    const float* __restrict__ bias,
    float* __restrict__ H, float* __restrict__ OUT)
{
    extern __shared__ __align__(1024) char sm[];
    const uint32_t smBase = smem_u32(sm);
    const int tid  = threadIdx.x;
    const int wid  = tid >> 5;
    const int lane = tid & 31;
    const int wm   = wid >> 2;          // 0..1  (64-row slab)
    const int wn   = wid & 3;           // 0..3  (32-col slab)
    const int n0   = blockIdx.x * 128;
    const int row0 = blockIdx.y * 128;

    float acc[4][4][4];
    #pragma unroll
    for (int i = 0; i < 4; i++)
        #pragma unroll
        for (int j = 0; j < 4; j++)
            #pragma unroll
            for (int k = 0; k < 4; k++) acc[i][j][k] = 0.f;

    // ldmatrix per-thread row/chunk decomposition
    const int lr  = lane & 7;
    const int ls1 = (lane >> 3) & 1;
    const int ls2 = lane >> 4;

    issue_stage(smBase, 0, 0, row0, n0, tid, Xhi, Xlo, Bhi, Blo);
    CPA_COMMIT();

    int buf = 0;
    for (int kc = 0; kc < 8; kc++) {
        if (kc < 7) {
            issue_stage(smBase, buf ^ 1, kc + 1, row0, n0, tid, Xhi, Xlo, Bhi, Blo);
            CPA_COMMIT();
            CPA_WAIT(1);
        } else {
            CPA_WAIT(0);
        }
        __syncthreads();

        uint32_t aB = smBase + buf * STAGE_BYTES;
        uint32_t bB = aB + 16384;

        #pragma unroll
        for (int kk = 0; kk < 2; kk++) {
            const int ch_hi = 2 * kk;        // 16B chunks 0..3 = hi, 4..7 = lo
            const int ch_lo = 4 + 2 * kk;

            uint32_t ahi[4][4], alo[4][4], bhi[2][4], blo[2][4];

            // A-hi fragments (rows = m, fragment tiles per ldmatrix.x4 spec)
            #pragma unroll
            for (int mf = 0; mf < 4; mf++) {
                int mrow = wm * 64 + mf * 16 + ls1 * 8 + lr;
                int ch   = ch_hi + ls2;
                ldsm_x4(ahi[mf][0], ahi[mf][1], ahi[mf][2], ahi[mf][3],
                        aB + SW(mrow * 128 + ch * 16));
            }
            // B-hi fragments (rows = n; one x4 covers two 8-col n-frags)
            #pragma unroll
            for (int np = 0; np < 2; np++) {
                int nrow = wn * 32 + np * 16 + ls2 * 8 + lr;
                int ch   = ch_hi + ls1;
                ldsm_x4(bhi[np][0], bhi[np][1], bhi[np][2], bhi[np][3],
                        bB + SW(nrow * 128 + ch * 16));
            }
            // hh
            #pragma unroll
            for (int mf = 0; mf < 4; mf++)
                #pragma unroll
                for (int nf = 0; nf < 4; nf++)
                    MMA_BF16(acc[mf][nf], ahi[mf],
                             bhi[nf >> 1][(nf & 1) * 2], bhi[nf >> 1][(nf & 1) * 2 + 1]);

            // A-lo, then lh
            #pragma unroll
            for (int mf = 0; mf < 4; mf++) {
                int mrow = wm * 64 + mf * 16 + ls1 * 8 + lr;
                int ch   = ch_lo + ls2;
                ldsm_x4(alo[mf][0], alo[mf][1], alo[mf][2], alo[mf][3],
                        aB + SW(mrow * 128 + ch * 16));
            }
            #pragma unroll
            for (int mf = 0; mf < 4; mf++)
                #pragma unroll
                for (int nf = 0; nf < 4; nf++)
                    MMA_BF16(acc[mf][nf], alo[mf],
                             bhi[nf >> 1][(nf & 1) * 2], bhi[nf >> 1][(nf & 1) * 2 + 1]);

            // B-lo, then hl
            #pragma unroll
            for (int np = 0; np < 2; np++) {
                int nrow = wn * 32 + np * 16 + ls2 * 8 + lr;
                int ch   = ch_lo + ls1;
                ldsm_x4(blo[np][0], blo[np][1], blo[np][2], blo[np][3],
                        bB + SW(nrow * 128 + ch * 16));
            }
            #pragma unroll
            for (int mf = 0; mf < 4; mf++)
                #pragma unroll
                for (int nf = 0; nf < 4; nf++)
                    MMA_BF16(acc[mf][nf], ahi[mf],
                             blo[nf >> 1][(nf & 1) * 2], blo[nf >> 1][(nf & 1) * 2 + 1]);
        }
        __syncthreads();
        buf ^= 1;
    }

    // ---- epilogue: direct fp32 stores ----
    const int g  = lane >> 2;
    const int tg = lane & 3;
    const bool isroot = (n0 >= 1024);

    #pragma unroll
    for (int nf = 0; nf < 4; nf++) {
        int col = n0 + wn * 32 + nf * 8 + tg * 2;
        float b0 = 0.f, b1 = 0.f;
        if (isroot) { b0 = bias[col - 1024]; b1 = bias[col - 1023]; }
        #pragma unroll
        for (int mf = 0; mf < 4; mf++) {
            int r0 = row0 + wm * 64 + mf * 16 + g;
            int r1 = r0 + 8;
            float2 v0 = make_float2(acc[mf][nf][0] + b0, acc[mf][nf][1] + b1);
            float2 v1 = make_float2(acc[mf][nf][2] + b0, acc[mf][nf][3] + b1);
            if (isroot) {
                if (r0 < N_NODES) *(float2*)(OUT + (size_t)r0 * 256 + col - 1024) = v0;
                if (r1 < N_NODES) *(float2*)(OUT + (size_t)r1 * 256 + col - 1024) = v1;
            } else {
                if (r0 < N_NODES) *(float2*)(H + (size_t)r0 * 1024 + col) = v0;
                if (r1 < N_NODES) *(float2*)(H + (size_t)r1 * 1024 + col) = v1;
            }
        }
    }
}

// ---------------------------------------------------------------------------
// Edge aggregation: OUT[dst] += inv_deg * H[src, etype*256 : +256]
// ---------------------------------------------------------------------------
__global__ void edge_kernel(const float* __restrict__ H,
                            const int* __restrict__ src,
                            const int* __restrict__ dst,
                            const int* __restrict__ et,
                            const int* __restrict__ cnt,
                            float* __restrict__ OUT)
{
    int e    = blockIdx.x * 4 + (threadIdx.x >> 6);
    int lane = threadIdx.x & 63;

    int s = src[e];
    int d = dst[e];
    int t = et[e];
    int c = cnt[d * N_REL + t];
    float inv = 1.0f / (float)(c > 1 ? c : 1);

    float4 v = *(const float4*)(H + (size_t)s * (N_REL * DIM) + t * DIM + lane * 4);
    v.x *= inv; v.y *= inv; v.z *= inv; v.w *= inv;

    float* p = OUT + (size_t)d * DIM + lane * 4;
    asm volatile("red.global.add.v4.f32 [%0], {%1, %2, %3, %4};"
                 :: "l"(p), "f"(v.x), "f"(v.y), "f"(v.z), "f"(v.w)
                 : "memory");
}

// ---------------------------------------------------------------------------
// LayerNorm + ELU + residual, fused with bf16 hi/lo split of the output
// ---------------------------------------------------------------------------
__device__ __forceinline__ float block_sum_256(float v, float* sh) {
    #pragma unroll
    for (int o = 16; o > 0; o >>= 1) v += __shfl_xor_sync(0xffffffffu, v, o);
    __syncthreads();
    if ((threadIdx.x & 31) == 0) sh[threadIdx.x >> 5] = v;
    __syncthreads();
    float s = 0.f;
    #pragma unroll
    for (int i = 0; i < 8; i++) s += sh[i];
    return s;
}

__global__ void ln_kernel(const float* __restrict__ OUT,
                          const float* __restrict__ Xin,
                          const float* __restrict__ gamma,
                          const float* __restrict__ beta,
                          float* __restrict__ Xout,
                          bf16* __restrict__ Xhi,
                          bf16* __restrict__ Xlo)
{
    __shared__ float sh[8];
    int n = blockIdx.x;
    int j = threadIdx.x;

    float v  = OUT[(size_t)n * DIM + j];
    float mu = block_sum_256(v, sh) * (1.0f / DIM);
    float dl = v - mu;
    float var = block_sum_256(dl * dl, sh) * (1.0f / DIM);

    float y = dl * rsqrtf(var + LN_EPS) * gamma[j] + beta[j];
    y = (y > 0.f) ? y : expm1f(y);
    float r = y + Xin[(size_t)n * DIM + j];
    size_t o = (size_t)n * DIM + j;
    Xout[o] = r;
    bf16 h, l;
    bf16_split(r, h, l);
    Xhi[o] = h;
    Xlo[o] = l;
}

// ---------------------------------------------------------------------------
// Driver
// ---------------------------------------------------------------------------
extern "C" void kernel_launch(void* const* d_in, const int* in_sizes, int n_in,
                              void* d_out, int out_size)
{
    const float* node    = (const float*)d_in[0];
    const float* weights = (const float*)d_in[1];   // [4,4,256,256]
    const float* roots   = (const float*)d_in[2];   // [4,256,256]
    const float* biases  = (const float*)d_in[3];   // [4,256]
    const float* gamma   = (const float*)d_in[4];   // [4,256]
    const float* beta    = (const float*)d_in[5];   // [4,256]
    const int*   eidx    = (const int*)d_in[6];     // [2,800000]
    const int*   etype   = (const int*)d_in[7];     // [800000]
    const int*   srcv    = eidx;
    const int*   dstv    = eidx + N_EDGES;
    float*       out     = (float*)d_out;

    float *H, *OUTb, *bufA, *bufB;
    bf16 *Xhi, *Xlo, *Bhi, *Blo;
    int* cnt;
    cudaGetSymbolAddress((void**)&H,    g_H);
    cudaGetSymbolAddress((void**)&OUTb, g_OUT);
    cudaGetSymbolAddress((void**)&bufA, g_bufA);
    cudaGetSymbolAddress((void**)&bufB, g_bufB);
    cudaGetSymbolAddress((void**)&Xhi,  g_Xhi);
    cudaGetSymbolAddress((void**)&Xlo,  g_Xlo);
    cudaGetSymbolAddress((void**)&Bhi,  g_Bhi);
    cudaGetSymbolAddress((void**)&Blo,  g_Blo);
    cudaGetSymbolAddress((void**)&cnt,  g_cnt);

    static int smem_set = 0;
    if (!smem_set) {
        cudaFuncSetAttribute(gemm_tc, cudaFuncAttributeMaxDynamicSharedMemorySize, SMEM_BYTES);
        smem_set = 1;
    }

    // in-degree histogram + operand splits (edge structure / weights: once per launch)
    zero_cnt_kernel<<<(N_NODES * N_REL + 255) / 256, 256>>>();
    count_kernel<<<(N_EDGES + 255) / 256, 256>>>(dstv, etype);
    wsplit_kernel<<<dim3(NCOL / 32, DIM / 32, DEPTH), dim3(32, 8)>>>(weights, roots, Bhi, Blo);
    xsplit_kernel<<<N_NODES * DIM / 256, 256>>>(node, Xhi, Xlo);

    for (int l = 0; l < DEPTH; l++) {
        const float* Xin  = (l == 0) ? node : ((l & 1) ? bufA : bufB);
        float*       Xout = (l == 3) ? out  : ((l & 1) ? bufB : bufA);

        gemm_tc<<<dim3(10, 391), 256, SMEM_BYTES>>>(
            Xhi, Xlo,
            Bhi + (size_t)l * NCOL * DIM,
            Blo + (size_t)l * NCOL * DIM,
            biases + l * DIM,
            H, OUTb);

        edge_kernel<<<N_EDGES / 4, 256>>>(H, srcv, dstv, etype, cnt, OUTb);

        ln_kernel<<<N_NODES, 256>>>(OUTb, Xin, gamma + l * DIM, beta + l * DIM,
                                    Xout, Xhi, Xlo);
    }
}

// round 5
// speedup vs baseline: 1.4769x; 1.0016x over previous
#include <cuda_runtime.h>
#include <cuda_bf16.h>
#include <math.h>
#include <stdint.h>

#define N_NODES 50000
#define N_EDGES 800000
#define DIM     256
#define DEPTH   4
#define N_REL   4
#define LN_EPS  1e-5f
#define NCOL    1280          // 4 relations * 256 + root 256

typedef __nv_bfloat16 bf16;

// ---------------------------------------------------------------------------
// Scratch (device globals: allocation-free per harness rules)
// ---------------------------------------------------------------------------
__device__ float g_H[(size_t)N_NODES * (N_REL * DIM)];   // per-relation transforms [N,1024]
__device__ float g_OUT[(size_t)N_NODES * DIM];           // agg + X@root + bias
__device__ float g_bufA[(size_t)N_NODES * DIM];          // X ping
__device__ float g_bufB[(size_t)N_NODES * DIM];          // X pong
__device__ bf16  g_Xhi[(size_t)N_NODES * DIM];           // bf16 hi split of X
__device__ bf16  g_Xlo[(size_t)N_NODES * DIM];           // bf16 lo split of X
__device__ bf16  g_Bhi[(size_t)DEPTH * NCOL * DIM];      // W^T hi  [l][n][k]
__device__ bf16  g_Blo[(size_t)DEPTH * NCOL * DIM];      // W^T lo
__device__ int   g_cnt[N_NODES * N_REL];

// ---------------------------------------------------------------------------
// PTX helpers (plain sm_80-era instructions -> assemble at target sm_103)
// ---------------------------------------------------------------------------
__device__ __forceinline__ uint32_t smem_u32(const void* p) {
    uint32_t a;
    asm("{ .reg .u64 t; cvta.to.shared.u64 t, %1; cvt.u32.u64 %0, t; }"
        : "=r"(a) : "l"(p));
    return a;
}

__device__ __forceinline__ void ldsm_x4(uint32_t& r0, uint32_t& r1,
                                        uint32_t& r2, uint32_t& r3, uint32_t addr) {
    asm volatile("ldmatrix.sync.aligned.m8n8.x4.shared.b16 {%0,%1,%2,%3}, [%4];"
                 : "=r"(r0), "=r"(r1), "=r"(r2), "=r"(r3) : "r"(addr));
}

#define MMA_BF16(c, a, b0v, b1v)                                             \
    asm volatile(                                                            \
        "mma.sync.aligned.m16n8k16.row.col.f32.bf16.bf16.f32 "               \
        "{%0,%1,%2,%3}, {%4,%5,%6,%7}, {%8,%9}, {%0,%1,%2,%3};"              \
        : "+f"((c)[0]), "+f"((c)[1]), "+f"((c)[2]), "+f"((c)[3])             \
        : "r"((a)[0]), "r"((a)[1]), "r"((a)[2]), "r"((a)[3]),                \
          "r"(b0v), "r"(b1v))

#define CPA16(dst, src)                                                      \
    asm volatile("cp.async.cg.shared.global [%0], [%1], 16;"                 \
                 :: "r"(dst), "l"(src) : "memory")
#define CPA_COMMIT() asm volatile("cp.async.commit_group;" ::: "memory")
#define CPA_WAIT(n)  asm volatile("cp.async.wait_group %0;" :: "n"(n) : "memory")

#define SW(o) ((uint32_t)(o) ^ ((((uint32_t)(o)) >> 3) & 0x70))

// ---------------------------------------------------------------------------
// Utility kernels
// ---------------------------------------------------------------------------
__global__ void zero_cnt_kernel() {
    int i = blockIdx.x * blockDim.x + threadIdx.x;
    if (i < N_NODES * N_REL) g_cnt[i] = 0;
}

__global__ void count_kernel(const int* __restrict__ dst, const int* __restrict__ et) {
    int e = blockIdx.x * blockDim.x + threadIdx.x;
    if (e < N_EDGES) atomicAdd(&g_cnt[dst[e] * N_REL + et[e]], 1);
}

__device__ __forceinline__ void bf16_split(float x, bf16& h, bf16& l) {
    h = __float2bfloat16(x);
    l = __float2bfloat16(x - __bfloat162float(h));
}

// split node embedding into bf16 hi/lo
__global__ void xsplit_kernel(const float* __restrict__ X,
                              bf16* __restrict__ hi, bf16* __restrict__ lo) {
    int i = blockIdx.x * 256 + threadIdx.x;
    bf16 h, l;
    bf16_split(X[i], h, l);
    hi[i] = h; lo[i] = l;
}

// transpose + split weights: Bhi/Blo[l][n][k] = split(W[l][rel][k][n] or root[l][k][n])
__global__ void wsplit_kernel(const float* __restrict__ W, const float* __restrict__ R,
                              bf16* __restrict__ Bhi, bf16* __restrict__ Blo) {
    __shared__ float t[32][33];
    int l  = blockIdx.z;
    int n0 = blockIdx.x * 32;
    int k0 = blockIdx.y * 32;
    int tx = threadIdx.x, ty = threadIdx.y;   // 32 x 8
    int rel = n0 >> 8;

    #pragma unroll
    for (int j = 0; j < 4; j++) {
        int k = k0 + ty + j * 8;
        float v;
        if (rel < 4)
            v = W[(((size_t)l * 4 + rel) * 256 + k) * 256 + (n0 & 255) + tx];
        else
            v = R[((size_t)l * 256 + k) * 256 + (n0 - 1024) + tx];
        t[ty + j * 8][tx] = v;
    }
    __syncthreads();
    #pragma unroll
    for (int j = 0; j < 4; j++) {
        int n = ty + j * 8;
        float x = t[tx][n];                    // = src[k0+tx][n0+n]
        bf16 h, lo;
        bf16_split(x, h, lo);
        size_t o = ((size_t)l * NCOL + n0 + n) * 256 + k0 + tx;
        Bhi[o] = h;
        Blo[o] = lo;
    }
}

// ---------------------------------------------------------------------------
// bf16 3-product GEMM via mma.sync: C[50000,1280] = X @ Wcat^T
//   C = Xhi*Bhi + Xlo*Bhi + Xhi*Blo  (fp32 accumulate)
// CTA tile 128x128, 8 warps (64x32 each), K chunks of 32 (hi|lo packed in
// one 128B SW128 row), 2-stage cp.async pipeline.
//   col tiles 0..7 -> g_H [N,1024];  col tiles 8..9 -> g_OUT (+bias)
// ---------------------------------------------------------------------------
#define STAGE_BYTES 32768          // A tile 16KB + B tile 16KB
#define SMEM_BYTES  (2 * STAGE_BYTES)

__device__ __forceinline__ void issue_stage(
    uint32_t smBase, int buf, int kc, int row0, int n0, int tid,
    const bf16* __restrict__ Xhi, const bf16* __restrict__ Xlo,
    const bf16* __restrict__ Bhi, const bf16* __restrict__ Blo)
{
    uint32_t aB = smBase + buf * STAGE_BYTES;
    uint32_t bB = aB + 16384;
    #pragma unroll
    for (int t = 0; t < 4; t++) {
        int j   = tid + t * 256;
        int row = j >> 3, ch = j & 7;
        int gr  = row0 + row;
        if (gr > N_NODES - 1) gr = N_NODES - 1;      // clamp; stores are guarded
        const bf16* src = (ch < 4 ? Xhi : Xlo) + (size_t)gr * 256 + kc * 32 + (ch & 3) * 8;
        CPA16(aB + SW(row * 128 + ch * 16), src);
    }
    #pragma unroll
    for (int t = 0; t < 4; t++) {
        int j   = tid + t * 256;
        int row = j >> 3, ch = j & 7;
        const bf16* src = (ch < 4 ? Bhi : Blo) + (size_t)(n0 + row) * 256 + kc * 32 + (ch & 3) * 8;
        CPA16(bB + SW(row * 128 + ch * 16), src);
    }
}

__global__ __launch_bounds__(256) void gemm_tc(
    const bf16* __restrict__ Xhi, const bf16* __restrict__ Xlo,
    const bf16* __restrict__ Bhi, const bf16* __restrict__ Blo,
    const float* __restrict__ bias,
    float* __restrict__ H, float* __restrict__ OUT)
{
    extern __shared__ __align__(1024) char sm[];
    const uint32_t smBase = smem_u32(sm);
    const int tid  = threadIdx.x;
    const int wid  = tid >> 5;
    const int lane = tid & 31;
    const int wm   = wid >> 2;          // 0..1  (64-row slab)
    const int wn   = wid & 3;           // 0..3  (32-col slab)
    const int n0   = blockIdx.x * 128;
    const int row0 = blockIdx.y * 128;

    float acc[4][4][4];
    #pragma unroll
    for (int i = 0; i < 4; i++)
        #pragma unroll
        for (int j = 0; j < 4; j++)
            #pragma unroll
            for (int k = 0; k < 4; k++) acc[i][j][k] = 0.f;

    // ldmatrix per-thread row/chunk decomposition
    const int lr  = lane & 7;
    const int ls1 = (lane >> 3) & 1;
    const int ls2 = lane >> 4;

    issue_stage(smBase, 0, 0, row0, n0, tid, Xhi, Xlo, Bhi, Blo);
    CPA_COMMIT();

    int buf = 0;
    for (int kc = 0; kc < 8; kc++) {
        if (kc < 7) {
            issue_stage(smBase, buf ^ 1, kc + 1, row0, n0, tid, Xhi, Xlo, Bhi, Blo);
            CPA_COMMIT();
            CPA_WAIT(1);
        } else {
            CPA_WAIT(0);
        }
        __syncthreads();

        uint32_t aB = smBase + buf * STAGE_BYTES;
        uint32_t bB = aB + 16384;

        #pragma unroll
        for (int kk = 0; kk < 2; kk++) {
            const int ch_hi = 2 * kk;        // 16B chunks 0..3 = hi, 4..7 = lo
            const int ch_lo = 4 + 2 * kk;

            uint32_t ahi[4][4], alo[4][4], bhi[2][4], blo[2][4];

            // A-hi fragments (rows = m, fragment tiles per ldmatrix.x4 spec)
            #pragma unroll
            for (int mf = 0; mf < 4; mf++) {
                int mrow = wm * 64 + mf * 16 + ls1 * 8 + lr;
                int ch   = ch_hi + ls2;
                ldsm_x4(ahi[mf][0], ahi[mf][1], ahi[mf][2], ahi[mf][3],
                        aB + SW(mrow * 128 + ch * 16));
            }
            // B-hi fragments (rows = n; one x4 covers two 8-col n-frags)
            #pragma unroll
            for (int np = 0; np < 2; np++) {
                int nrow = wn * 32 + np * 16 + ls2 * 8 + lr;
                int ch   = ch_hi + ls1;
                ldsm_x4(bhi[np][0], bhi[np][1], bhi[np][2], bhi[np][3],
                        bB + SW(nrow * 128 + ch * 16));
            }
            // hh
            #pragma unroll
            for (int mf = 0; mf < 4; mf++)
                #pragma unroll
                for (int nf = 0; nf < 4; nf++)
                    MMA_BF16(acc[mf][nf], ahi[mf],
                             bhi[nf >> 1][(nf & 1) * 2], bhi[nf >> 1][(nf & 1) * 2 + 1]);

            // A-lo, then lh
            #pragma unroll
            for (int mf = 0; mf < 4; mf++) {
                int mrow = wm * 64 + mf * 16 + ls1 * 8 + lr;
                int ch   = ch_lo + ls2;
                ldsm_x4(alo[mf][0], alo[mf][1], alo[mf][2], alo[mf][3],
                        aB + SW(mrow * 128 + ch * 16));
            }
            #pragma unroll
            for (int mf = 0; mf < 4; mf++)
                #pragma unroll
                for (int nf = 0; nf < 4; nf++)
                    MMA_BF16(acc[mf][nf], alo[mf],
                             bhi[nf >> 1][(nf & 1) * 2], bhi[nf >> 1][(nf & 1) * 2 + 1]);

            // B-lo, then hl
            #pragma unroll
            for (int np = 0; np < 2; np++) {
                int nrow = wn * 32 + np * 16 + ls2 * 8 + lr;
                int ch   = ch_lo + ls1;
                ldsm_x4(blo[np][0], blo[np][1], blo[np][2], blo[np][3],
                        bB + SW(nrow * 128 + ch * 16));
            }
            #pragma unroll
            for (int mf = 0; mf < 4; mf++)
                #pragma unroll
                for (int nf = 0; nf < 4; nf++)
                    MMA_BF16(acc[mf][nf], ahi[mf],
                             blo[nf >> 1][(nf & 1) * 2], blo[nf >> 1][(nf & 1) * 2 + 1]);
        }
        __syncthreads();
        buf ^= 1;
    }

    // ---- epilogue: direct fp32 stores ----
    const int g  = lane >> 2;
    const int tg = lane & 3;
    const bool isroot = (n0 >= 1024);

    #pragma unroll
    for (int nf = 0; nf < 4; nf++) {
        int col = n0 + wn * 32 + nf * 8 + tg * 2;
        float b0 = 0.f, b1 = 0.f;
        if (isroot) { b0 = bias[col - 1024]; b1 = bias[col - 1023]; }
        #pragma unroll
        for (int mf = 0; mf < 4; mf++) {
            int r0 = row0 + wm * 64 + mf * 16 + g;
            int r1 = r0 + 8;
            float2 v0 = make_float2(acc[mf][nf][0] + b0, acc[mf][nf][1] + b1);
            float2 v1 = make_float2(acc[mf][nf][2] + b0, acc[mf][nf][3] + b1);
            if (isroot) {
                if (r0 < N_NODES) *(float2*)(OUT + (size_t)r0 * 256 + col - 1024) = v0;
                if (r1 < N_NODES) *(float2*)(OUT + (size_t)r1 * 256 + col - 1024) = v1;
            } else {
                if (r0 < N_NODES) *(float2*)(H + (size_t)r0 * 1024 + col) = v0;
                if (r1 < N_NODES) *(float2*)(H + (size_t)r1 * 1024 + col) = v1;
            }
        }
    }
}

// ---------------------------------------------------------------------------
// Edge aggregation: OUT[dst] += inv_deg * H[src, etype*256 : +256]
// ---------------------------------------------------------------------------
__global__ void edge_kernel(const float* __restrict__ H,
                            const int* __restrict__ src,
                            const int* __restrict__ dst,
                            const int* __restrict__ et,
                            const int* __restrict__ cnt,
                            float* __restrict__ OUT)
{
    int e    = blockIdx.x * 4 + (threadIdx.x >> 6);
    int lane = threadIdx.x & 63;

    int s = src[e];
    int d = dst[e];
    int t = et[e];
    int c = cnt[d * N_REL + t];
    float inv = 1.0f / (float)(c > 1 ? c : 1);

    float4 v = *(const float4*)(H + (size_t)s * (N_REL * DIM) + t * DIM + lane * 4);
    v.x *= inv; v.y *= inv; v.z *= inv; v.w *= inv;

    float* p = OUT + (size_t)d * DIM + lane * 4;
    asm volatile("red.global.add.v4.f32 [%0], {%1, %2, %3, %4};"
                 :: "l"(p), "f"(v.x), "f"(v.y), "f"(v.z), "f"(v.w)
                 : "memory");
}

// ---------------------------------------------------------------------------
// LayerNorm + ELU + residual, fused with bf16 hi/lo split of the output
// ---------------------------------------------------------------------------
__device__ __forceinline__ float block_sum_256(float v, float* sh) {
    #pragma unroll
    for (int o = 16; o > 0; o >>= 1) v += __shfl_xor_sync(0xffffffffu, v, o);
    __syncthreads();
    if ((threadIdx.x & 31) == 0) sh[threadIdx.x >> 5] = v;
    __syncthreads();
    float s = 0.f;
    #pragma unroll
    for (int i = 0; i < 8; i++) s += sh[i];
    return s;
}

__global__ void ln_kernel(const float* __restrict__ OUT,
                          const float* __restrict__ Xin,
                          const float* __restrict__ gamma,
                          const float* __restrict__ beta,
                          float* __restrict__ Xout,
                          bf16* __restrict__ Xhi,
                          bf16* __restrict__ Xlo)
{
    __shared__ float sh[8];
    int n = blockIdx.x;
    int j = threadIdx.x;

    float v  = OUT[(size_t)n * DIM + j];
    float mu = block_sum_256(v, sh) * (1.0f / DIM);
    float dl = v - mu;
    float var = block_sum_256(dl * dl, sh) * (1.0f / DIM);

    float y = dl * rsqrtf(var + LN_EPS) * gamma[j] + beta[j];
    y = (y > 0.f) ? y : expm1f(y);
    float r = y + Xin[(size_t)n * DIM + j];
    size_t o = (size_t)n * DIM + j;
    Xout[o] = r;
    bf16 h, l;
    bf16_split(r, h, l);
    Xhi[o] = h;
    Xlo[o] = l;
}

// ---------------------------------------------------------------------------
// Driver
// ---------------------------------------------------------------------------
extern "C" void kernel_launch(void* const* d_in, const int* in_sizes, int n_in,
                              void* d_out, int out_size)
{
    const float* node    = (const float*)d_in[0];
    const float* weights = (const float*)d_in[1];   // [4,4,256,256]
    const float* roots   = (const float*)d_in[2];   // [4,256,256]
    const float* biases  = (const float*)d_in[3];   // [4,256]
    const float* gamma   = (const float*)d_in[4];   // [4,256]
    const float* beta    = (const float*)d_in[5];   // [4,256]
    const int*   eidx    = (const int*)d_in[6];     // [2,800000]
    const int*   etype   = (const int*)d_in[7];     // [800000]
    const int*   srcv    = eidx;
    const int*   dstv    = eidx + N_EDGES;
    float*       out     = (float*)d_out;

    float *H, *OUTb, *bufA, *bufB;
    bf16 *Xhi, *Xlo, *Bhi, *Blo;
    int* cnt;
    cudaGetSymbolAddress((void**)&H,    g_H);
    cudaGetSymbolAddress((void**)&OUTb, g_OUT);
    cudaGetSymbolAddress((void**)&bufA, g_bufA);
    cudaGetSymbolAddress((void**)&bufB, g_bufB);
    cudaGetSymbolAddress((void**)&Xhi,  g_Xhi);
    cudaGetSymbolAddress((void**)&Xlo,  g_Xlo);
    cudaGetSymbolAddress((void**)&Bhi,  g_Bhi);
    cudaGetSymbolAddress((void**)&Blo,  g_Blo);
    cudaGetSymbolAddress((void**)&cnt,  g_cnt);

    static int smem_set = 0;
    if (!smem_set) {
        cudaFuncSetAttribute(gemm_tc, cudaFuncAttributeMaxDynamicSharedMemorySize, SMEM_BYTES);
        smem_set = 1;
    }

    // in-degree histogram + operand splits (edge structure / weights: once per launch)
    zero_cnt_kernel<<<(N_NODES * N_REL + 255) / 256, 256>>>();
    count_kernel<<<(N_EDGES + 255) / 256, 256>>>(dstv, etype);
    wsplit_kernel<<<dim3(NCOL / 32, DIM / 32, DEPTH), dim3(32, 8)>>>(weights, roots, Bhi, Blo);
    xsplit_kernel<<<N_NODES * DIM / 256, 256>>>(node, Xhi, Xlo);

    for (int l = 0; l < DEPTH; l++) {
        const float* Xin  = (l == 0) ? node : ((l & 1) ? bufA : bufB);
        float*       Xout = (l == 3) ? out  : ((l & 1) ? bufB : bufA);

        gemm_tc<<<dim3(10, 391), 256, SMEM_BYTES>>>(
            Xhi, Xlo,
            Bhi + (size_t)l * NCOL * DIM,
            Blo + (size_t)l * NCOL * DIM,
            biases + l * DIM,
            H, OUTb);

        edge_kernel<<<N_EDGES / 4, 256>>>(H, srcv, dstv, etype, cnt, OUTb);

        ln_kernel<<<N_NODES, 256>>>(OUTb, Xin, gamma + l * DIM, beta + l * DIM,
                                    Xout, Xhi, Xlo);
    }
}

// round 6
// speedup vs baseline: 1.4786x; 1.0011x over previous
#include <cuda_runtime.h>
#include <cuda_bf16.h>
#include <math.h>
#include <stdint.h>

#define N_NODES 50000
#define N_EDGES 800000
#define DIM     256
#define DEPTH   4
#define N_REL   4
#define LN_EPS  1e-5f
#define NCOL    1280          // 4 relations * 256 + root 256

typedef __nv_bfloat16 bf16;

// ---------------------------------------------------------------------------
// Scratch (device globals: allocation-free per harness rules)
// ---------------------------------------------------------------------------
__device__ float g_H[(size_t)N_NODES * (N_REL * DIM)];   // per-relation transforms [N,1024]
__device__ float g_OUT[(size_t)N_NODES * DIM];           // agg + X@root + bias
__device__ float g_bufA[(size_t)N_NODES * DIM];          // X ping
__device__ float g_bufB[(size_t)N_NODES * DIM];          // X pong
__device__ bf16  g_Xhi[(size_t)N_NODES * DIM];           // bf16 hi split of X
__device__ bf16  g_Xlo[(size_t)N_NODES * DIM];           // bf16 lo split of X
__device__ bf16  g_Bhi[(size_t)DEPTH * NCOL * DIM];      // W^T hi  [l][n][k]
__device__ bf16  g_Blo[(size_t)DEPTH * NCOL * DIM];      // W^T lo
__device__ int   g_cnt[N_NODES * N_REL];

// ---------------------------------------------------------------------------
// PTX helpers (plain sm_80-era instructions -> assemble at target sm_103)
// ---------------------------------------------------------------------------
__device__ __forceinline__ uint32_t smem_u32(const void* p) {
    uint32_t a;
    asm("{ .reg .u64 t; cvta.to.shared.u64 t, %1; cvt.u32.u64 %0, t; }"
        : "=r"(a) : "l"(p));
    return a;
}

__device__ __forceinline__ void ldsm_x4(uint32_t& r0, uint32_t& r1,
                                        uint32_t& r2, uint32_t& r3, uint32_t addr) {
    asm volatile("ldmatrix.sync.aligned.m8n8.x4.shared.b16 {%0,%1,%2,%3}, [%4];"
                 : "=r"(r0), "=r"(r1), "=r"(r2), "=r"(r3) : "r"(addr));
}

#define MMA_BF16(c, a, b0v, b1v)                                             \
    asm volatile(                                                            \
        "mma.sync.aligned.m16n8k16.row.col.f32.bf16.bf16.f32 "               \
        "{%0,%1,%2,%3}, {%4,%5,%6,%7}, {%8,%9}, {%0,%1,%2,%3};"              \
        : "+f"((c)[0]), "+f"((c)[1]), "+f"((c)[2]), "+f"((c)[3])             \
        : "r"((a)[0]), "r"((a)[1]), "r"((a)[2]), "r"((a)[3]),                \
          "r"(b0v), "r"(b1v))

#define CPA16(dst, src)                                                      \
    asm volatile("cp.async.cg.shared.global [%0], [%1], 16;"                 \
                 :: "r"(dst), "l"(src) : "memory")
#define CPA_COMMIT() asm volatile("cp.async.commit_group;" ::: "memory")
#define CPA_WAIT(n)  asm volatile("cp.async.wait_group %0;" :: "n"(n) : "memory")

#define SW(o) ((uint32_t)(o) ^ ((((uint32_t)(o)) >> 3) & 0x70))

// ---------------------------------------------------------------------------
// Utility kernels
// ---------------------------------------------------------------------------
__global__ void zero_cnt_kernel() {
    int i = blockIdx.x * blockDim.x + threadIdx.x;
    if (i < N_NODES * N_REL) g_cnt[i] = 0;
}

__global__ void count_kernel(const int* __restrict__ dst, const int* __restrict__ et) {
    int e = blockIdx.x * blockDim.x + threadIdx.x;
    if (e < N_EDGES) atomicAdd(&g_cnt[dst[e] * N_REL + et[e]], 1);
}

__device__ __forceinline__ void bf16_split(float x, bf16& h, bf16& l) {
    h = __float2bfloat16(x);
    l = __float2bfloat16(x - __bfloat162float(h));
}

// split node embedding into bf16 hi/lo
__global__ void xsplit_kernel(const float* __restrict__ X,
                              bf16* __restrict__ hi, bf16* __restrict__ lo) {
    int i = blockIdx.x * 256 + threadIdx.x;
    bf16 h, l;
    bf16_split(X[i], h, l);
    hi[i] = h; lo[i] = l;
}

// transpose + split weights: Bhi/Blo[l][n][k] = split(W[l][rel][k][n] or root[l][k][n])
__global__ void wsplit_kernel(const float* __restrict__ W, const float* __restrict__ R,
                              bf16* __restrict__ Bhi, bf16* __restrict__ Blo) {
    __shared__ float t[32][33];
    int l  = blockIdx.z;
    int n0 = blockIdx.x * 32;
    int k0 = blockIdx.y * 32;
    int tx = threadIdx.x, ty = threadIdx.y;   // 32 x 8
    int rel = n0 >> 8;

    #pragma unroll
    for (int j = 0; j < 4; j++) {
        int k = k0 + ty + j * 8;
        float v;
        if (rel < 4)
            v = W[(((size_t)l * 4 + rel) * 256 + k) * 256 + (n0 & 255) + tx];
        else
            v = R[((size_t)l * 256 + k) * 256 + (n0 - 1024) + tx];
        t[ty + j * 8][tx] = v;
    }
    __syncthreads();
    #pragma unroll
    for (int j = 0; j < 4; j++) {
        int n = ty + j * 8;
        float x = t[tx][n];                    // = src[k0+tx][n0+n]
        bf16 h, lo;
        bf16_split(x, h, lo);
        size_t o = ((size_t)l * NCOL + n0 + n) * 256 + k0 + tx;
        Bhi[o] = h;
        Blo[o] = lo;
    }
}

// ---------------------------------------------------------------------------
// bf16 3-product GEMM via mma.sync: C[50000,1280] = X @ Wcat^T
//   C = Xhi*Bhi + Xlo*Bhi + Xhi*Blo  (fp32 accumulate)
// CTA tile 128x128, 8 warps (64x32 each), K chunks of 32 (hi|lo packed in
// one 128B SW128 row), 2-stage cp.async pipeline.
//   col tiles 0..7 -> g_H [N,1024];  col tiles 8..9 -> g_OUT (+bias)
// ---------------------------------------------------------------------------
#define STAGE_BYTES 32768          // A tile 16KB + B tile 16KB
#define SMEM_BYTES  (2 * STAGE_BYTES)

__device__ __forceinline__ void issue_stage(
    uint32_t smBase, int buf, int kc, int row0, int n0, int tid,
    const bf16* __restrict__ Xhi, const bf16* __restrict__ Xlo,
    const bf16* __restrict__ Bhi, const bf16* __restrict__ Blo)
{
    uint32_t aB = smBase + buf * STAGE_BYTES;
    uint32_t bB = aB + 16384;
    #pragma unroll
    for (int t = 0; t < 4; t++) {
        int j   = tid + t * 256;
        int row = j >> 3, ch = j & 7;
        int gr  = row0 + row;
        if (gr > N_NODES - 1) gr = N_NODES - 1;      // clamp; stores are guarded
        const bf16* src = (ch < 4 ? Xhi : Xlo) + (size_t)gr * 256 + kc * 32 + (ch & 3) * 8;
        CPA16(aB + SW(row * 128 + ch * 16), src);
    }
    #pragma unroll
    for (int t = 0; t < 4; t++) {
        int j   = tid + t * 256;
        int row = j >> 3, ch = j & 7;
        const bf16* src = (ch < 4 ? Bhi : Blo) + (size_t)(n0 + row) * 256 + kc * 32 + (ch & 3) * 8;
        CPA16(bB + SW(row * 128 + ch * 16), src);
    }
}

__global__ __launch_bounds__(256) void gemm_tc(
    const bf16* __restrict__ Xhi, const bf16* __restrict__ Xlo,
    const bf16* __restrict__ Bhi, const bf16* __restrict__ Blo,
    const float* __restrict__ bias,
    float* __restrict__ H, float* __restrict__ OUT)
{
    extern __shared__ __align__(1024) char sm[];
    const uint32_t smBase = smem_u32(sm);
    const int tid  = threadIdx.x;
    const int wid  = tid >> 5;
    const int lane = tid & 31;
    const int wm   = wid >> 2;          // 0..1  (64-row slab)
    const int wn   = wid & 3;           // 0..3  (32-col slab)
    const int n0   = blockIdx.x * 128;
    const int row0 = blockIdx.y * 128;

    float acc[4][4][4];
    #pragma unroll
    for (int i = 0; i < 4; i++)
        #pragma unroll
        for (int j = 0; j < 4; j++)
            #pragma unroll
            for (int k = 0; k < 4; k++) acc[i][j][k] = 0.f;

    // ldmatrix per-thread row/chunk decomposition
    const int lr  = lane & 7;
    const int ls1 = (lane >> 3) & 1;
    const int ls2 = lane >> 4;

    issue_stage(smBase, 0, 0, row0, n0, tid, Xhi, Xlo, Bhi, Blo);
    CPA_COMMIT();

    int buf = 0;
    for (int kc = 0; kc < 8; kc++) {
        if (kc < 7) {
            issue_stage(smBase, buf ^ 1, kc + 1, row0, n0, tid, Xhi, Xlo, Bhi, Blo);
            CPA_COMMIT();
            CPA_WAIT(1);
        } else {
            CPA_WAIT(0);
        }
        __syncthreads();

        uint32_t aB = smBase + buf * STAGE_BYTES;
        uint32_t bB = aB + 16384;

        #pragma unroll
        for (int kk = 0; kk < 2; kk++) {
            const int ch_hi = 2 * kk;        // 16B chunks 0..3 = hi, 4..7 = lo
            const int ch_lo = 4 + 2 * kk;

            uint32_t ahi[4][4], alo[4][4], bhi[2][4], blo[2][4];

            // A-hi fragments (rows = m, fragment tiles per ldmatrix.x4 spec)
            #pragma unroll
            for (int mf = 0; mf < 4; mf++) {
                int mrow = wm * 64 + mf * 16 + ls1 * 8 + lr;
                int ch   = ch_hi + ls2;
                ldsm_x4(ahi[mf][0], ahi[mf][1], ahi[mf][2], ahi[mf][3],
                        aB + SW(mrow * 128 + ch * 16));
            }
            // B-hi fragments (rows = n; one x4 covers two 8-col n-frags)
            #pragma unroll
            for (int np = 0; np < 2; np++) {
                int nrow = wn * 32 + np * 16 + ls2 * 8 + lr;
                int ch   = ch_hi + ls1;
                ldsm_x4(bhi[np][0], bhi[np][1], bhi[np][2], bhi[np][3],
                        bB + SW(nrow * 128 + ch * 16));
            }
            // hh
            #pragma unroll
            for (int mf = 0; mf < 4; mf++)
                #pragma unroll
                for (int nf = 0; nf < 4; nf++)
                    MMA_BF16(acc[mf][nf], ahi[mf],
                             bhi[nf >> 1][(nf & 1) * 2], bhi[nf >> 1][(nf & 1) * 2 + 1]);

            // A-lo, then lh
            #pragma unroll
            for (int mf = 0; mf < 4; mf++) {
                int mrow = wm * 64 + mf * 16 + ls1 * 8 + lr;
                int ch   = ch_lo + ls2;
                ldsm_x4(alo[mf][0], alo[mf][1], alo[mf][2], alo[mf][3],
                        aB + SW(mrow * 128 + ch * 16));
            }
            #pragma unroll
            for (int mf = 0; mf < 4; mf++)
                #pragma unroll
                for (int nf = 0; nf < 4; nf++)
                    MMA_BF16(acc[mf][nf], alo[mf],
                             bhi[nf >> 1][(nf & 1) * 2], bhi[nf >> 1][(nf & 1) * 2 + 1]);

            // B-lo, then hl
            #pragma unroll
            for (int np = 0; np < 2; np++) {
                int nrow = wn * 32 + np * 16 + ls2 * 8 + lr;
                int ch   = ch_lo + ls1;
                ldsm_x4(blo[np][0], blo[np][1], blo[np][2], blo[np][3],
                        bB + SW(nrow * 128 + ch * 16));
            }
            #pragma unroll
            for (int mf = 0; mf < 4; mf++)
                #pragma unroll
                for (int nf = 0; nf < 4; nf++)
                    MMA_BF16(acc[mf][nf], ahi[mf],
                             blo[nf >> 1][(nf & 1) * 2], blo[nf >> 1][(nf & 1) * 2 + 1]);
        }
        __syncthreads();
        buf ^= 1;
    }

    // ---- epilogue: direct fp32 stores ----
    const int g  = lane >> 2;
    const int tg = lane & 3;
    const bool isroot = (n0 >= 1024);

    #pragma unroll
    for (int nf = 0; nf < 4; nf++) {
        int col = n0 + wn * 32 + nf * 8 + tg * 2;
        float b0 = 0.f, b1 = 0.f;
        if (isroot) { b0 = bias[col - 1024]; b1 = bias[col - 1023]; }
        #pragma unroll
        for (int mf = 0; mf < 4; mf++) {
            int r0 = row0 + wm * 64 + mf * 16 + g;
            int r1 = r0 + 8;
            float2 v0 = make_float2(acc[mf][nf][0] + b0, acc[mf][nf][1] + b1);
            float2 v1 = make_float2(acc[mf][nf][2] + b0, acc[mf][nf][3] + b1);
            if (isroot) {
                if (r0 < N_NODES) *(float2*)(OUT + (size_t)r0 * 256 + col - 1024) = v0;
                if (r1 < N_NODES) *(float2*)(OUT + (size_t)r1 * 256 + col - 1024) = v1;
            } else {
                if (r0 < N_NODES) *(float2*)(H + (size_t)r0 * 1024 + col) = v0;
                if (r1 < N_NODES) *(float2*)(H + (size_t)r1 * 1024 + col) = v1;
            }
        }
    }
}

// ---------------------------------------------------------------------------
// Edge aggregation: OUT[dst] += inv_deg * H[src, etype*256 : +256]
// ---------------------------------------------------------------------------
__global__ void edge_kernel(const float* __restrict__ H,
                            const int* __restrict__ src,
                            const int* __restrict__ dst,
                            const int* __restrict__ et,
                            const int* __restrict__ cnt,
                            float* __restrict__ OUT)
{
    int e    = blockIdx.x * 4 + (threadIdx.x >> 6);
    int lane = threadIdx.x & 63;

    int s = src[e];
    int d = dst[e];
    int t = et[e];
    int c = cnt[d * N_REL + t];
    float inv = 1.0f / (float)(c > 1 ? c : 1);

    float4 v = *(const float4*)(H + (size_t)s * (N_REL * DIM) + t * DIM + lane * 4);
    v.x *= inv; v.y *= inv; v.z *= inv; v.w *= inv;

    float* p = OUT + (size_t)d * DIM + lane * 4;
    asm volatile("red.global.add.v4.f32 [%0], {%1, %2, %3, %4};"
                 :: "l"(p), "f"(v.x), "f"(v.y), "f"(v.z), "f"(v.w)
                 : "memory");
}

// ---------------------------------------------------------------------------
// LayerNorm + ELU + residual, fused with bf16 hi/lo split of the output
// ---------------------------------------------------------------------------
__device__ __forceinline__ float block_sum_256(float v, float* sh) {
    #pragma unroll
    for (int o = 16; o > 0; o >>= 1) v += __shfl_xor_sync(0xffffffffu, v, o);
    __syncthreads();
    if ((threadIdx.x & 31) == 0) sh[threadIdx.x >> 5] = v;
    __syncthreads();
    float s = 0.f;
    #pragma unroll
    for (int i = 0; i < 8; i++) s += sh[i];
    return s;
}

__global__ void ln_kernel(const float* __restrict__ OUT,
                          const float* __restrict__ Xin,
                          const float* __restrict__ gamma,
                          const float* __restrict__ beta,
                          float* __restrict__ Xout,
                          bf16* __restrict__ Xhi,
                          bf16* __restrict__ Xlo)
{
    __shared__ float sh[8];
    int n = blockIdx.x;
    int j = threadIdx.x;

    float v  = OUT[(size_t)n * DIM + j];
    float mu = block_sum_256(v, sh) * (1.0f / DIM);
    float dl = v - mu;
    float var = block_sum_256(dl * dl, sh) * (1.0f / DIM);

    float y = dl * rsqrtf(var + LN_EPS) * gamma[j] + beta[j];
    y = (y > 0.f) ? y : expm1f(y);
    float r = y + Xin[(size_t)n * DIM + j];
    size_t o = (size_t)n * DIM + j;
    Xout[o] = r;
    bf16 h, l;
    bf16_split(r, h, l);
    Xhi[o] = h;
    Xlo[o] = l;
}

// ---------------------------------------------------------------------------
// Driver
// ---------------------------------------------------------------------------
extern "C" void kernel_launch(void* const* d_in, const int* in_sizes, int n_in,
                              void* d_out, int out_size)
{
    const float* node    = (const float*)d_in[0];
    const float* weights = (const float*)d_in[1];   // [4,4,256,256]
    const float* roots   = (const float*)d_in[2];   // [4,256,256]
    const float* biases  = (const float*)d_in[3];   // [4,256]
    const float* gamma   = (const float*)d_in[4];   // [4,256]
    const float* beta    = (const float*)d_in[5];   // [4,256]
    const int*   eidx    = (const int*)d_in[6];     // [2,800000]
    const int*   etype   = (const int*)d_in[7];     // [800000]
    const int*   srcv    = eidx;
    const int*   dstv    = eidx + N_EDGES;
    float*       out     = (float*)d_out;

    float *H, *OUTb, *bufA, *bufB;
    bf16 *Xhi, *Xlo, *Bhi, *Blo;
    int* cnt;
    cudaGetSymbolAddress((void**)&H,    g_H);
    cudaGetSymbolAddress((void**)&OUTb, g_OUT);
    cudaGetSymbolAddress((void**)&bufA, g_bufA);
    cudaGetSymbolAddress((void**)&bufB, g_bufB);
    cudaGetSymbolAddress((void**)&Xhi,  g_Xhi);
    cudaGetSymbolAddress((void**)&Xlo,  g_Xlo);
    cudaGetSymbolAddress((void**)&Bhi,  g_Bhi);
    cudaGetSymbolAddress((void**)&Blo,  g_Blo);
    cudaGetSymbolAddress((void**)&cnt,  g_cnt);

    static int smem_set = 0;
    if (!smem_set) {
        cudaFuncSetAttribute(gemm_tc, cudaFuncAttributeMaxDynamicSharedMemorySize, SMEM_BYTES);
        smem_set = 1;
    }

    // in-degree histogram + operand splits (edge structure / weights: once per launch)
    zero_cnt_kernel<<<(N_NODES * N_REL + 255) / 256, 256>>>();
    count_kernel<<<(N_EDGES + 255) / 256, 256>>>(dstv, etype);
    wsplit_kernel<<<dim3(NCOL / 32, DIM / 32, DEPTH), dim3(32, 8)>>>(weights, roots, Bhi, Blo);
    xsplit_kernel<<<N_NODES * DIM / 256, 256>>>(node, Xhi, Xlo);

    for (int l = 0; l < DEPTH; l++) {
        const float* Xin  = (l == 0) ? node : ((l & 1) ? bufA : bufB);
        float*       Xout = (l == 3) ? out  : ((l & 1) ? bufB : bufA);

        gemm_tc<<<dim3(10, 391), 256, SMEM_BYTES>>>(
            Xhi, Xlo,
            Bhi + (size_t)l * NCOL * DIM,
            Blo + (size_t)l * NCOL * DIM,
            biases + l * DIM,
            H, OUTb);

        edge_kernel<<<N_EDGES / 4, 256>>>(H, srcv, dstv, etype, cnt, OUTb);

        ln_kernel<<<N_NODES, 256>>>(OUTb, Xin, gamma + l * DIM, beta + l * DIM,
                                    Xout, Xhi, Xlo);
    }
}